// round 2
// baseline (speedup 1.0000x reference)
#include <cuda_runtime.h>
#include <math.h>

#define NN      50000
#define NE      800000
#define F1      128
#define H       64
#define NCLS    40
#define NPAD    50176   // padded node count (mult of 64 and 4)

// Scratch pool: S1[NPAD*128] | T1[NPAD*128] | S2[NPAD*64] | T2[NPAD*64] | deg[NPAD]
#define OFF_S1  ((size_t)0)
#define OFF_T1  ((size_t)NPAD * 128)
#define OFF_S2  ((size_t)NPAD * 256)
#define OFF_T2  ((size_t)NPAD * 320)
#define OFF_DEG ((size_t)NPAD * 384)
#define SCR_FLOATS ((size_t)NPAD * 385)

__device__ float g_scr[SCR_FLOATS];
__device__ float g_h[(size_t)NPAD * H];

// ---------------------------------------------------------------------------
// vectorized float4 global reduction (sm_90+)
__device__ __forceinline__ void red_add_v4(float* addr, float a, float b, float c, float d) {
    asm volatile("red.global.add.v4.f32 [%0], {%1,%2,%3,%4};"
                 :: "l"(addr), "f"(a), "f"(b), "f"(c), "f"(d) : "memory");
}

// ---------------------------------------------------------------------------
__global__ __launch_bounds__(256) void zero_scr_kernel() {
    size_t i = (size_t)blockIdx.x * blockDim.x + threadIdx.x;
    size_t n4 = SCR_FLOATS / 4;
    float4* p = reinterpret_cast<float4*>(g_scr);
    float4 z = make_float4(0.f, 0.f, 0.f, 0.f);
    for (; i < n4; i += (size_t)gridDim.x * blockDim.x) p[i] = z;
}

// ---------------------------------------------------------------------------
// Scatter layer 1: one warp per edge. Each lane handles one float4 of the
// 128-float x row. S1[dst] += x[src]; T1[dst] += v * x[src]; deg[dst] += 1.
__global__ __launch_bounds__(256) void scatter1_kernel(
    const float* __restrict__ x,
    const int*   __restrict__ src,
    const int*   __restrict__ dst,
    const float* __restrict__ ea)
{
    int warp = (blockIdx.x * blockDim.x + threadIdx.x) >> 5;
    int lane = threadIdx.x & 31;
    if (warp >= NE) return;
    int s = __ldg(src + warp);
    int d = __ldg(dst + warp);
    float v = __ldg(ea + warp);
    float4 xv = __ldg(reinterpret_cast<const float4*>(x + (size_t)s * F1) + lane);
    float* Sp = g_scr + OFF_S1 + (size_t)d * F1 + lane * 4;
    float* Tp = g_scr + OFF_T1 + (size_t)d * F1 + lane * 4;
    red_add_v4(Sp, xv.x, xv.y, xv.z, xv.w);
    red_add_v4(Tp, v * xv.x, v * xv.y, v * xv.z, v * xv.w);
    if (lane == 0) atomicAdd(g_scr + OFF_DEG + d, 1.0f);
}

// ---------------------------------------------------------------------------
// Dense layer 1: h = elu( (S1@W0 + T1@dW)/deg + x@root1 + bias1 )
// block = 256 threads, 64 nodes/block, 64 outputs. Thread tile = 4 nodes x 4 outs.
// Weights (3 x 128 x 64 fp32 = 96KB) in dynamic smem.
__global__ __launch_bounds__(256) void dense1_kernel(
    const float* __restrict__ x,
    const float* __restrict__ W1,
    const float* __restrict__ root1,
    const float* __restrict__ bias1)
{
    extern __shared__ float sw[];
    float* sW0 = sw;                 // W1[0]
    float* sdW = sw + F1 * H;        // W1[1] - W1[0]
    float* sR  = sw + 2 * F1 * H;    // root1
    for (int i = threadIdx.x; i < F1 * H; i += 256) {
        float w0 = W1[i];
        sW0[i] = w0;
        sdW[i] = W1[F1 * H + i] - w0;
        sR[i]  = root1[i];
    }
    __syncthreads();

    int og = threadIdx.x & 15;   // 16 groups x 4 outputs
    int ng = threadIdx.x >> 4;   // 16 groups x 4 nodes
    int nb = blockIdx.x * 64 + ng * 4;

    const float* rS[4]; const float* rT[4]; const float* rX[4];
    #pragma unroll
    for (int i = 0; i < 4; i++) {
        int n = nb + i; if (n > NN - 1) n = NN - 1;   // clamp for padding rows
        rS[i] = g_scr + OFF_S1 + (size_t)n * F1;
        rT[i] = g_scr + OFF_T1 + (size_t)n * F1;
        rX[i] = x + (size_t)n * F1;
    }

    float accM[4][4] = {}, accR[4][4] = {};
    #pragma unroll 4
    for (int k = 0; k < F1; k++) {
        float w0[4], dw[4], wr[4];
        #pragma unroll
        for (int j = 0; j < 4; j++) {
            int o = og * 4 + j;
            w0[j] = sW0[k * H + o];
            dw[j] = sdW[k * H + o];
            wr[j] = sR [k * H + o];
        }
        #pragma unroll
        for (int i = 0; i < 4; i++) {
            float sv = __ldg(rS[i] + k);
            float tv = __ldg(rT[i] + k);
            float xv = __ldg(rX[i] + k);
            #pragma unroll
            for (int j = 0; j < 4; j++) {
                accM[i][j] += sv * w0[j] + tv * dw[j];
                accR[i][j] += xv * wr[j];
            }
        }
    }

    #pragma unroll
    for (int i = 0; i < 4; i++) {
        int n = nb + i;
        if (n >= NN) continue;
        float deg = g_scr[OFF_DEG + n];
        float inv = 1.0f / fmaxf(deg, 1.0f);
        #pragma unroll
        for (int j = 0; j < 4; j++) {
            int o = og * 4 + j;
            float val = accM[i][j] * inv + accR[i][j] + __ldg(bias1 + o);
            val = (val > 0.f) ? val : expm1f(val);
            g_h[(size_t)n * H + o] = val;
        }
    }
}

// ---------------------------------------------------------------------------
// Scatter layer 2: 16 lanes per edge (64 floats = 16 float4).
__global__ __launch_bounds__(256) void scatter2_kernel(
    const int*   __restrict__ src,
    const int*   __restrict__ dst,
    const float* __restrict__ ea)
{
    int t = blockIdx.x * blockDim.x + threadIdx.x;
    int e = t >> 4;
    int lane = t & 15;
    if (e >= NE) return;
    int s = __ldg(src + e);
    int d = __ldg(dst + e);
    float v = __ldg(ea + e);
    float4 hv = __ldg(reinterpret_cast<const float4*>(g_h + (size_t)s * H) + lane);
    float* Sp = g_scr + OFF_S2 + (size_t)d * H + lane * 4;
    float* Tp = g_scr + OFF_T2 + (size_t)d * H + lane * 4;
    red_add_v4(Sp, hv.x, hv.y, hv.z, hv.w);
    red_add_v4(Tp, v * hv.x, v * hv.y, v * hv.z, v * hv.w);
}

// ---------------------------------------------------------------------------
// Dense layer 2: out = (S2@W0 + T2@dW)/deg + h@root2 + bias2
// block = 256 threads, 64 nodes/block. Thread tile = 2 nodes x 5 outs.
__global__ __launch_bounds__(256) void dense2_kernel(
    const float* __restrict__ W2,
    const float* __restrict__ root2,
    const float* __restrict__ bias2,
    float* __restrict__ out)
{
    __shared__ float sW0[H * NCLS];
    __shared__ float sdW[H * NCLS];
    __shared__ float sR [H * NCLS];
    for (int i = threadIdx.x; i < H * NCLS; i += 256) {
        float w0 = W2[i];
        sW0[i] = w0;
        sdW[i] = W2[H * NCLS + i] - w0;
        sR[i]  = root2[i];
    }
    __syncthreads();

    int og = threadIdx.x & 7;    // 8 groups x 5 outputs
    int ng = threadIdx.x >> 3;   // 32 groups x 2 nodes
    int nb = blockIdx.x * 64 + ng * 2;

    const float* rS[2]; const float* rT[2]; const float* rH[2];
    #pragma unroll
    for (int i = 0; i < 2; i++) {
        int n = nb + i; if (n > NN - 1) n = NN - 1;
        rS[i] = g_scr + OFF_S2 + (size_t)n * H;
        rT[i] = g_scr + OFF_T2 + (size_t)n * H;
        rH[i] = g_h + (size_t)n * H;
    }

    float accM[2][5] = {}, accR[2][5] = {};
    #pragma unroll 4
    for (int k = 0; k < H; k++) {
        float w0[5], dw[5], wr[5];
        #pragma unroll
        for (int j = 0; j < 5; j++) {
            int o = og * 5 + j;
            w0[j] = sW0[k * NCLS + o];
            dw[j] = sdW[k * NCLS + o];
            wr[j] = sR [k * NCLS + o];
        }
        #pragma unroll
        for (int i = 0; i < 2; i++) {
            float sv = __ldg(rS[i] + k);
            float tv = __ldg(rT[i] + k);
            float hv = __ldg(rH[i] + k);
            #pragma unroll
            for (int j = 0; j < 5; j++) {
                accM[i][j] += sv * w0[j] + tv * dw[j];
                accR[i][j] += hv * wr[j];
            }
        }
    }

    #pragma unroll
    for (int i = 0; i < 2; i++) {
        int n = nb + i;
        if (n >= NN) continue;
        float deg = g_scr[OFF_DEG + n];
        float inv = 1.0f / fmaxf(deg, 1.0f);
        #pragma unroll
        for (int j = 0; j < 5; j++) {
            int o = og * 5 + j;
            out[(size_t)n * NCLS + o] = accM[i][j] * inv + accR[i][j] + __ldg(bias2 + o);
        }
    }
}

// ---------------------------------------------------------------------------
extern "C" void kernel_launch(void* const* d_in, const int* in_sizes, int n_in,
                              void* d_out, int out_size)
{
    const float* x     = (const float*)d_in[0];
    const int*   eidx  = (const int*)  d_in[1];
    const float* ea    = (const float*)d_in[2];
    const float* W1    = (const float*)d_in[3];
    const float* root1 = (const float*)d_in[4];
    const float* bias1 = (const float*)d_in[5];
    const float* W2    = (const float*)d_in[6];
    const float* root2 = (const float*)d_in[7];
    const float* bias2 = (const float*)d_in[8];
    float* out = (float*)d_out;

    const int* src = eidx;
    const int* dst = eidx + NE;

    // allow 96KB dynamic smem for dense1 (idempotent, immediate API)
    cudaFuncSetAttribute(dense1_kernel, cudaFuncAttributeMaxDynamicSharedMemorySize,
                         3 * F1 * H * (int)sizeof(float));

    zero_scr_kernel<<<2048, 256>>>();
    scatter1_kernel<<<(NE * 32) / 256, 256>>>(x, src, dst, ea);
    dense1_kernel<<<(NN + 63) / 64, 256, 3 * F1 * H * sizeof(float)>>>(x, W1, root1, bias1);
    scatter2_kernel<<<(NE * 16) / 256, 256>>>(src, dst, ea);
    dense2_kernel<<<(NN + 63) / 64, 256>>>(W2, root2, bias2, out);
}

// round 3
// speedup vs baseline: 1.5987x; 1.5987x over previous
#include <cuda_runtime.h>
#include <math.h>

#define NN    50000
#define NE    800000
#define F1    128
#define H     64
#define NCLS  40
#define NPAD  50176       // multiple of 64

#define Y_COLS 192        // [ x@W0 | x@(W1-W0) | x@root1 ]
#define Z_COLS 128        // [ h@W0' | h@(W1'-W0') | h@root2 | pad8 ]

// zeroed scratch: A1[NPAD*64] | A2[NPAD*40] | deg[NPAD]
#define OFF_A1  ((size_t)0)
#define OFF_A2  ((size_t)NPAD * 64)
#define OFF_DEG ((size_t)NPAD * 104)
#define SCR_FLOATS ((size_t)NPAD * 105)

__device__ float g_scr[SCR_FLOATS];
__device__ float g_y[(size_t)NPAD * Y_COLS];
__device__ float g_h[(size_t)NPAD * H];
__device__ float g_z[(size_t)NPAD * Z_COLS];

// ---------------------------------------------------------------------------
__device__ __forceinline__ void red_add_v4(float* addr, float a, float b, float c, float d) {
    asm volatile("red.global.add.v4.f32 [%0], {%1,%2,%3,%4};"
                 :: "l"(addr), "f"(a), "f"(b), "f"(c), "f"(d) : "memory");
}

// ---------------------------------------------------------------------------
__global__ __launch_bounds__(256) void zero_scr_kernel() {
    size_t i = (size_t)blockIdx.x * blockDim.x + threadIdx.x;
    size_t n4 = SCR_FLOATS / 4;
    float4* p = reinterpret_cast<float4*>(g_scr);
    float4 z = make_float4(0.f, 0.f, 0.f, 0.f);
    for (; i < n4; i += (size_t)gridDim.x * blockDim.x) p[i] = z;
}

// ---------------------------------------------------------------------------
// proj1: y[n, 0:192] = x[n] @ [W0 | W1-W0 | root1]   (K=128)
// block = 256 thr, tile 64 nodes x 96 outs (grid.y = 2), thread tile 4x6.
__global__ __launch_bounds__(256) void proj1_kernel(
    const float* __restrict__ x,
    const float* __restrict__ W1,
    const float* __restrict__ root1)
{
    extern __shared__ float smem[];
    float* sw = smem;               // [128][96]
    float* sx = smem + 128 * 96;    // [64][36]  (node-major, padded)
    int tid = threadIdx.x;
    int ob = blockIdx.y * 96;

    for (int idx = tid; idx < 128 * 96; idx += 256) {
        int k = idx / 96, oc = idx % 96, o = ob + oc;
        float val;
        if (o < 64)       val = W1[k * 64 + o];
        else if (o < 128) { int oo = o - 64; val = W1[128 * 64 + k * 64 + oo] - W1[k * 64 + oo]; }
        else              val = root1[k * 64 + (o - 128)];
        sw[idx] = val;
    }

    int og = tid & 15;   // 16 groups x 6 outs
    int ng = tid >> 4;   // 16 groups x 4 nodes
    int nb = blockIdx.x * 64;
    float acc[4][6] = {};

    for (int kk = 0; kk < 128; kk += 32) {
        __syncthreads();
        #pragma unroll
        for (int r = 0; r < 2; r++) {
            int i = tid * 2 + r;            // [0, 512)
            int row = i >> 3, c = i & 7;
            int n = nb + row; if (n > NN - 1) n = NN - 1;
            float4 xv = __ldg(reinterpret_cast<const float4*>(x + (size_t)n * F1 + kk) + c);
            *reinterpret_cast<float4*>(sx + row * 36 + c * 4) = xv;
        }
        __syncthreads();
        #pragma unroll
        for (int k2 = 0; k2 < 32; k2++) {
            int kg = kk + k2;
            float w[6];
            *reinterpret_cast<float2*>(w + 0) = *reinterpret_cast<float2*>(sw + kg * 96 + og * 6);
            *reinterpret_cast<float2*>(w + 2) = *reinterpret_cast<float2*>(sw + kg * 96 + og * 6 + 2);
            *reinterpret_cast<float2*>(w + 4) = *reinterpret_cast<float2*>(sw + kg * 96 + og * 6 + 4);
            #pragma unroll
            for (int i = 0; i < 4; i++) {
                float xr = sx[(ng * 4 + i) * 36 + k2];
                #pragma unroll
                for (int j = 0; j < 6; j++) acc[i][j] += xr * w[j];
            }
        }
    }

    #pragma unroll
    for (int i = 0; i < 4; i++) {
        int n = nb + ng * 4 + i;
        float* yp = g_y + (size_t)n * Y_COLS + ob + og * 6;
        #pragma unroll
        for (int j = 0; j < 6; j++) yp[j] = acc[i][j];
    }
}

// ---------------------------------------------------------------------------
// scatter1: A1[dst] += y0[src] + v*yd[src];  deg[dst] += 1.   16 lanes/edge.
__global__ __launch_bounds__(256) void scatter1_kernel(
    const int* __restrict__ src,
    const int* __restrict__ dst,
    const float* __restrict__ ea)
{
    int t = blockIdx.x * 256 + threadIdx.x;
    int e = t >> 4, lane = t & 15;
    if (e >= NE) return;
    int s = __ldg(src + e), d = __ldg(dst + e);
    float v = __ldg(ea + e);
    const float4* yr = reinterpret_cast<const float4*>(g_y + (size_t)s * Y_COLS);
    float4 y0 = yr[lane];
    float4 yd = yr[16 + lane];
    red_add_v4(g_scr + OFF_A1 + (size_t)d * 64 + lane * 4,
               fmaf(v, yd.x, y0.x), fmaf(v, yd.y, y0.y),
               fmaf(v, yd.z, y0.z), fmaf(v, yd.w, y0.w));
    if (lane == 0) atomicAdd(g_scr + OFF_DEG + d, 1.0f);
}

// ---------------------------------------------------------------------------
// elu1: h = elu(A1/deg + yroot + bias1)     (float4 per thread)
__global__ __launch_bounds__(256) void elu1_kernel(const float* __restrict__ bias1)
{
    int t = blockIdx.x * 256 + threadIdx.x;       // NN*16 threads
    if (t >= NN * 16) return;
    int n = t >> 4, q = t & 15;
    float inv = 1.0f / fmaxf(g_scr[OFF_DEG + n], 1.0f);
    float4 a = *reinterpret_cast<const float4*>(g_scr + OFF_A1 + (size_t)n * 64 + q * 4);
    float4 yr = *reinterpret_cast<const float4*>(g_y + (size_t)n * Y_COLS + 128 + q * 4);
    float4 b = __ldg(reinterpret_cast<const float4*>(bias1) + q);
    float4 o;
    o.x = a.x * inv + yr.x + b.x;
    o.y = a.y * inv + yr.y + b.y;
    o.z = a.z * inv + yr.z + b.z;
    o.w = a.w * inv + yr.w + b.w;
    o.x = o.x > 0.f ? o.x : expm1f(o.x);
    o.y = o.y > 0.f ? o.y : expm1f(o.y);
    o.z = o.z > 0.f ? o.z : expm1f(o.z);
    o.w = o.w > 0.f ? o.w : expm1f(o.w);
    *reinterpret_cast<float4*>(g_h + (size_t)n * H + q * 4) = o;
}

// ---------------------------------------------------------------------------
// proj2: z[n, 0:128] = h[n] @ [W0' | W1'-W0' | root2 | 0]   (K=64)
// block = 256 thr, tile 64 nodes x 64 outs (grid.y = 2), thread tile 4x4.
__global__ __launch_bounds__(256) void proj2_kernel(
    const float* __restrict__ W2,
    const float* __restrict__ root2)
{
    __shared__ float sw[64 * 64];
    __shared__ float sx[64 * 36];
    int tid = threadIdx.x;
    int ob = blockIdx.y * 64;

    for (int idx = tid; idx < 64 * 64; idx += 256) {
        int k = idx >> 6, oc = idx & 63, o = ob + oc;
        float val;
        if (o < 40)      val = W2[k * 40 + o];
        else if (o < 80) { int oo = o - 40; val = W2[64 * 40 + k * 40 + oo] - W2[k * 40 + oo]; }
        else if (o < 120) val = root2[k * 40 + (o - 80)];
        else             val = 0.f;
        sw[idx] = val;
    }

    int og = tid & 15;   // 16 x 4 outs
    int ng = tid >> 4;   // 16 x 4 nodes
    int nb = blockIdx.x * 64;
    float acc[4][4] = {};

    for (int kk = 0; kk < 64; kk += 32) {
        __syncthreads();
        #pragma unroll
        for (int r = 0; r < 2; r++) {
            int i = tid * 2 + r;
            int row = i >> 3, c = i & 7;
            int n = nb + row; if (n > NN - 1) n = NN - 1;
            float4 hv = *reinterpret_cast<const float4*>(g_h + (size_t)n * H + kk + c * 4);
            *reinterpret_cast<float4*>(sx + row * 36 + c * 4) = hv;
        }
        __syncthreads();
        #pragma unroll
        for (int k2 = 0; k2 < 32; k2++) {
            int kg = kk + k2;
            float4 wv = *reinterpret_cast<float4*>(sw + kg * 64 + og * 4);
            #pragma unroll
            for (int i = 0; i < 4; i++) {
                float xr = sx[(ng * 4 + i) * 36 + k2];
                acc[i][0] += xr * wv.x;
                acc[i][1] += xr * wv.y;
                acc[i][2] += xr * wv.z;
                acc[i][3] += xr * wv.w;
            }
        }
    }

    #pragma unroll
    for (int i = 0; i < 4; i++) {
        int n = nb + ng * 4 + i;
        float* zp = g_z + (size_t)n * Z_COLS + ob + og * 4;
        #pragma unroll
        for (int j = 0; j < 4; j++) zp[j] = acc[i][j];
    }
}

// ---------------------------------------------------------------------------
// scatter2: A2[dst] += z0[src] + v*zd[src].   10 lanes/edge (40 floats).
__global__ __launch_bounds__(256) void scatter2_kernel(
    const int* __restrict__ src,
    const int* __restrict__ dst,
    const float* __restrict__ ea)
{
    unsigned t = blockIdx.x * 256 + threadIdx.x;
    unsigned e = t / 10u;
    unsigned lane = t - e * 10u;
    if (e >= NE) return;
    int s = __ldg(src + e), d = __ldg(dst + e);
    float v = __ldg(ea + e);
    const float4* zr = reinterpret_cast<const float4*>(g_z + (size_t)s * Z_COLS);
    float4 z0 = zr[lane];
    float4 zd = zr[10 + lane];
    red_add_v4(g_scr + OFF_A2 + (size_t)d * 40 + lane * 4,
               fmaf(v, zd.x, z0.x), fmaf(v, zd.y, z0.y),
               fmaf(v, zd.z, z0.z), fmaf(v, zd.w, z0.w));
}

// ---------------------------------------------------------------------------
// final: out = A2/deg + zroot + bias2
__global__ __launch_bounds__(256) void final_kernel(
    const float* __restrict__ bias2, float* __restrict__ out)
{
    unsigned t = blockIdx.x * 256 + threadIdx.x;   // NN*10 threads
    if (t >= NN * 10) return;
    unsigned n = t / 10u;
    unsigned l = t - n * 10u;
    float inv = 1.0f / fmaxf(g_scr[OFF_DEG + n], 1.0f);
    float4 a = *reinterpret_cast<const float4*>(g_scr + OFF_A2 + (size_t)n * 40 + l * 4);
    float4 zr = *reinterpret_cast<const float4*>(g_z + (size_t)n * Z_COLS + 80 + l * 4);
    float4 b = __ldg(reinterpret_cast<const float4*>(bias2) + l);
    float4 o;
    o.x = a.x * inv + zr.x + b.x;
    o.y = a.y * inv + zr.y + b.y;
    o.z = a.z * inv + zr.z + b.z;
    o.w = a.w * inv + zr.w + b.w;
    *reinterpret_cast<float4*>(out + (size_t)n * 40 + l * 4) = o;
}

// ---------------------------------------------------------------------------
extern "C" void kernel_launch(void* const* d_in, const int* in_sizes, int n_in,
                              void* d_out, int out_size)
{
    const float* x     = (const float*)d_in[0];
    const int*   eidx  = (const int*)  d_in[1];
    const float* ea    = (const float*)d_in[2];
    const float* W1    = (const float*)d_in[3];
    const float* root1 = (const float*)d_in[4];
    const float* bias1 = (const float*)d_in[5];
    const float* W2    = (const float*)d_in[6];
    const float* root2 = (const float*)d_in[7];
    const float* bias2 = (const float*)d_in[8];
    float* out = (float*)d_out;

    const int* src = eidx;
    const int* dst = eidx + NE;

    const int p1_smem = (128 * 96 + 64 * 36) * (int)sizeof(float);  // 58368 B
    cudaFuncSetAttribute(proj1_kernel, cudaFuncAttributeMaxDynamicSharedMemorySize, p1_smem);

    zero_scr_kernel<<<2048, 256>>>();
    proj1_kernel<<<dim3(NPAD / 64, 2), 256, p1_smem>>>(x, W1, root1);
    scatter1_kernel<<<(NE * 16) / 256, 256>>>(src, dst, ea);
    elu1_kernel<<<(NN * 16 + 255) / 256, 256>>>(bias1);
    proj2_kernel<<<dim3(NPAD / 64, 2), 256>>>(W2, root2);
    scatter2_kernel<<<(NE * 10 + 255) / 256, 256>>>(src, dst, ea);
    final_kernel<<<(NN * 10 + 255) / 256, 256>>>(bias2, out);
}